// round 11
// baseline (speedup 1.0000x reference)
#include <cuda_runtime.h>

typedef unsigned long long ull;

#define N_ 128
#define L_ 160
#define E_ 512
#define HE_ 512
#define HD_ 1024
#define T_ 128
#define LN_ (L_*N_)
#define G4E_ 2048
#define NB_ 128u

// ---------------- scratch (device globals) ----------------
__device__ __align__(16) float g_xs[LN_*E_];
__device__ __align__(16) float g_G[2][(size_t)LN_*G4E_];
__device__ __align__(16) float g_h1[(size_t)LN_*2*HE_];
__device__ __align__(16) float g_enc[(size_t)LN_*2*HE_];
__device__ __align__(16) float g_eh[2][2][N_*HE_];   // [phase][dir]
__device__ __align__(16) float g_ec[2][N_*HE_];      // [dir]
__device__ __align__(16) float g_dh[2][N_*HD_];
__device__ __align__(16) float g_dc[N_*HD_];
__device__ __align__(16) float g_wiT[T_][4*HD_];     // transposed dec_wih (2MB)
__device__ int   g_amax[N_];
__device__ float g_lterm[L_*N_];

__device__ unsigned g_bcnt = 0;
__device__ volatile unsigned g_bgen = 0;

__device__ __forceinline__ void fma2(ull& d, ull a, ull b){
    asm("fma.rn.f32x2 %0, %1, %2, %0;" : "+l"(d) : "l"(a), "l"(b));
}
__device__ __forceinline__ ull dup2(float x){
    ull r; asm("mov.b64 %0, {%1, %1};" : "=l"(r) : "f"(x)); return r;
}
__device__ __forceinline__ float2 unpack2(ull v){
    float2 r; asm("mov.b64 {%0, %1}, %2;" : "=f"(r.x), "=f"(r.y) : "l"(v)); return r;
}
__device__ __forceinline__ float sigf(float x){ return 1.f/(1.f+expf(-x)); }

__device__ __forceinline__ void gridbar(){
    __syncthreads();
    if (threadIdx.x == 0) {
        unsigned g = g_bgen;
        __threadfence();
        if (atomicAdd(&g_bcnt, 1u) == NB_ - 1u) {
            atomicExch(&g_bcnt, 0u);
            __threadfence();
            g_bgen = g + 1u;
        } else {
            while (g_bgen == g) { }
        }
        __threadfence();
    }
    __syncthreads();
}

// ---------------- embedding ----------------
__global__ void k_embed(const int* __restrict__ ids, const float* __restrict__ embed)
{
    int i = blockIdx.x*blockDim.x + threadIdx.x;
    const int tot = LN_*E_/4;
    if (i >= tot) return;
    int e4 = i % (E_/4);
    int ln = i / (E_/4);
    int l = ln / N_, n = ln % N_;
    int id = ids[n*L_ + l];
    reinterpret_cast<float4*>(g_xs)[i] =
        reinterpret_cast<const float4*>(embed + (size_t)id*E_)[e4];
}

// ---------------- dwih transpose: g_wiT[idx][col] = dwih[col*T + idx] ----------------
__global__ void k_wiT(const float* __restrict__ dwih)
{
    int i = blockIdx.x*blockDim.x + threadIdx.x;
    if (i < 4*HD_*T_) {
        int col = i >> 7;
        int idx = i & 127;
        g_wiT[idx][col] = dwih[i];
    }
}

// ---------------- big input GEMM (R9/R10 version, fma 66%) ----------------
__global__ __launch_bounds__(256) void k_gemm_bias(int asel, const float* __restrict__ Ball,
                                                   const float* __restrict__ biasall, int K)
{
    const float* A = asel ? g_h1 : g_xs;
    int z = blockIdx.z;
    const float* B = Ball + (size_t)z * G4E_ * K;
    const float* bias = biasall + z * G4E_;
    float* C = g_G[z];
    int m0 = blockIdx.y * 128, n0 = blockIdx.x * 128;
    __shared__ float As[8][132];
    __shared__ float Bs[8][132];
    int tid = threadIdx.x;
    int lr = tid >> 1, lk = (tid & 1) * 4;
    int ry = (tid >> 4) * 8;
    int c4 = (tid & 15) * 4;
    ull acc[4][8];
    #pragma unroll
    for (int p = 0; p < 4; p++)
        #pragma unroll
        for (int j = 0; j < 8; j++) acc[p][j] = 0ull;
    const float* Arow = A + (size_t)(m0+lr)*K + lk;
    const float* Brow = B + (size_t)(n0+lr)*K + lk;
    #pragma unroll 1
    for (int kc = 0; kc < K; kc += 8) {
        float4 av = *(const float4*)(Arow + kc);
        float4 bv = *(const float4*)(Brow + kc);
        __syncthreads();
        As[lk+0][lr]=av.x; As[lk+1][lr]=av.y; As[lk+2][lr]=av.z; As[lk+3][lr]=av.w;
        Bs[lk+0][lr]=bv.x; Bs[lk+1][lr]=bv.y; Bs[lk+2][lr]=bv.z; Bs[lk+3][lr]=bv.w;
        __syncthreads();
        #pragma unroll
        for (int kk = 0; kk < 8; kk++) {
            ulonglong2 aA = *(const ulonglong2*)&As[kk][ry];
            ulonglong2 aB = *(const ulonglong2*)&As[kk][ry+4];
            float4 b0 = *(const float4*)&Bs[kk][c4];
            float4 b1 = *(const float4*)&Bs[kk][64+c4];
            ull q[8] = {dup2(b0.x),dup2(b0.y),dup2(b0.z),dup2(b0.w),
                        dup2(b1.x),dup2(b1.y),dup2(b1.z),dup2(b1.w)};
            ull ar[4] = {aA.x, aA.y, aB.x, aB.y};
            #pragma unroll
            for (int p = 0; p < 4; p++)
                #pragma unroll
                for (int j = 0; j < 8; j++)
                    fma2(acc[p][j], ar[p], q[j]);
        }
    }
    float4 bia0 = *(const float4*)(bias + n0 + c4);
    float4 bia1 = *(const float4*)(bias + n0 + 64 + c4);
    #pragma unroll
    for (int p = 0; p < 4; p++) {
        float2 v[8];
        #pragma unroll
        for (int j = 0; j < 8; j++) v[j] = unpack2(acc[p][j]);
        float* C0 = C + (size_t)(m0+ry+2*p)*G4E_ + n0;
        float* C1 = C + (size_t)(m0+ry+2*p+1)*G4E_ + n0;
        *(float4*)(C0 + c4)    = make_float4(v[0].x+bia0.x, v[1].x+bia0.y, v[2].x+bia0.z, v[3].x+bia0.w);
        *(float4*)(C0 + 64+c4) = make_float4(v[4].x+bia1.x, v[5].x+bia1.y, v[6].x+bia1.z, v[7].x+bia1.w);
        *(float4*)(C1 + c4)    = make_float4(v[0].y+bia0.x, v[1].y+bia0.y, v[2].y+bia0.z, v[3].y+bia0.w);
        *(float4*)(C1 + 64+c4) = make_float4(v[4].y+bia1.x, v[5].y+bia1.y, v[6].y+bia1.z, v[7].y+bia1.w);
    }
}

// ================= persistent encoder: 512 threads, K-split-8, 3-stage pipeline =================
__global__ __launch_bounds__(512) void k_encP(int layer, const float* __restrict__ whh_all)
{
    extern __shared__ float sm[];
    float* Bs = sm;                        // [512][36]
    float* As = sm + 512*36;               // [3][32][132]
    float* gs = As + 3*32*132;             // [128][36]

    const int b  = blockIdx.x;
    const int d  = b >> 6;
    const int u0 = (b & 63) * 8;
    const int tid = threadIdx.x;
    const int kg = tid >> 6;               // K-group 0..7
    const int slot = tid & 63;
    const int r0 = (slot >> 2) * 8;
    const int c0 = (slot & 3) * 8;
    const int sr = tid & 127;              // stage row
    const int sg = tid >> 7;               // stage group 0..3

    {
        const float* wb = whh_all + (size_t)d * (4*HE_) * HE_;
        for (int s = tid; s < 32*(HE_/4); s += 512) {
            int c = s / (HE_/4), k4 = s % (HE_/4);
            int wr = (c >> 3) * HE_ + u0 + (c & 7);
            float4 v = *(const float4*)(wb + (size_t)wr*HE_ + k4*4);
            Bs[(k4*4+0)*36 + c] = v.x;
            Bs[(k4*4+1)*36 + c] = v.y;
            Bs[(k4*4+2)*36 + c] = v.z;
            Bs[(k4*4+3)*36 + c] = v.w;
        }
    }
    float* obase = layer ? g_enc : g_h1;
    __syncthreads();

    for (int t = 0; t < L_; t++) {
        const int t_eff = d ? (L_-1-t) : t;
        ull acc[4][8];
        #pragma unroll
        for (int p = 0; p < 4; p++)
            #pragma unroll
            for (int j = 0; j < 8; j++) acc[p][j] = 0ull;

        if (t > 0) {
            const float* hin = g_eh[t & 1][d];
            const float* base0 = hin + (size_t)sr*HE_ + (2*sg)*64;
            const float* base1 = hin + (size_t)sr*HE_ + (2*sg+1)*64;
            float4 ra0, ra1;
            // stage chunks 0 and 1
            ra0 = __ldcg((const float4*)(base0));
            ra1 = __ldcg((const float4*)(base1));
            {
                float* q0 = As + (8*sg)*132 + sr;
                float* q1 = As + (8*sg+4)*132 + sr;
                q0[0]=ra0.x; q0[132]=ra0.y; q0[264]=ra0.z; q0[396]=ra0.w;
                q1[0]=ra1.x; q1[132]=ra1.y; q1[264]=ra1.z; q1[396]=ra1.w;
            }
            ra0 = __ldcg((const float4*)(base0 + 4));
            ra1 = __ldcg((const float4*)(base1 + 4));
            {
                float* q0 = As + 4224 + (8*sg)*132 + sr;
                float* q1 = As + 4224 + (8*sg+4)*132 + sr;
                q0[0]=ra0.x; q0[132]=ra0.y; q0[264]=ra0.z; q0[396]=ra0.w;
                q1[0]=ra1.x; q1[132]=ra1.y; q1[264]=ra1.z; q1[396]=ra1.w;
            }
            __syncthreads();
            #pragma unroll 1
            for (int ch = 0; ch < 16; ch++) {
                if (ch + 2 < 16) {
                    ra0 = __ldcg((const float4*)(base0 + (ch+2)*4));
                    ra1 = __ldcg((const float4*)(base1 + (ch+2)*4));
                }
                int cb = ch % 3;
                const float* ap = As + cb*4224 + (kg*4)*132 + r0;
                const float* bp = Bs + (kg*64 + ch*4)*36 + c0;
                #pragma unroll
                for (int kk = 0; kk < 4; kk++) {
                    ulonglong2 aA = *(const ulonglong2*)(ap + kk*132);
                    ulonglong2 aB = *(const ulonglong2*)(ap + kk*132 + 4);
                    float4 b0 = *(const float4*)(bp + kk*36);
                    float4 b1 = *(const float4*)(bp + kk*36 + 4);
                    ull q[8] = {dup2(b0.x),dup2(b0.y),dup2(b0.z),dup2(b0.w),
                                dup2(b1.x),dup2(b1.y),dup2(b1.z),dup2(b1.w)};
                    ull ar[4] = {aA.x, aA.y, aB.x, aB.y};
                    #pragma unroll
                    for (int p = 0; p < 4; p++)
                        #pragma unroll
                        for (int j = 0; j < 8; j++)
                            fma2(acc[p][j], ar[p], q[j]);
                }
                if (ch + 2 < 16) {
                    int nb = (ch + 2) % 3;
                    float* q0 = As + nb*4224 + (8*sg)*132 + sr;
                    float* q1 = As + nb*4224 + (8*sg+4)*132 + sr;
                    q0[0]=ra0.x; q0[132]=ra0.y; q0[264]=ra0.z; q0[396]=ra0.w;
                    q1[0]=ra1.x; q1[132]=ra1.y; q1[264]=ra1.z; q1[396]=ra1.w;
                }
                __syncthreads();
            }
        }
        // reduce 8 K-group partials into gs
        #pragma unroll 1
        for (int ph2 = 0; ph2 < 8; ph2++) {
            if (kg == ph2) {
                #pragma unroll
                for (int p = 0; p < 4; p++) {
                    float2 v[8];
                    #pragma unroll
                    for (int j = 0; j < 8; j++) v[j] = unpack2(acc[p][j]);
                    float* w0 = gs + (r0+2*p)*36 + c0;
                    float* w1 = gs + (r0+2*p+1)*36 + c0;
                    float4 x0 = make_float4(v[0].x,v[1].x,v[2].x,v[3].x);
                    float4 x1 = make_float4(v[4].x,v[5].x,v[6].x,v[7].x);
                    float4 y0 = make_float4(v[0].y,v[1].y,v[2].y,v[3].y);
                    float4 y1 = make_float4(v[4].y,v[5].y,v[6].y,v[7].y);
                    if (ph2 == 0) {
                        *(float4*)w0 = x0; *(float4*)(w0+4) = x1;
                        *(float4*)w1 = y0; *(float4*)(w1+4) = y1;
                    } else {
                        float4 o0 = *(const float4*)w0, o1 = *(const float4*)(w0+4);
                        float4 o2 = *(const float4*)w1, o3 = *(const float4*)(w1+4);
                        *(float4*)w0 = make_float4(o0.x+x0.x,o0.y+x0.y,o0.z+x0.z,o0.w+x0.w);
                        *(float4*)(w0+4) = make_float4(o1.x+x1.x,o1.y+x1.y,o1.z+x1.z,o1.w+x1.w);
                        *(float4*)w1 = make_float4(o2.x+y0.x,o2.y+y0.y,o2.z+y0.z,o2.w+y0.w);
                        *(float4*)(w1+4) = make_float4(o3.x+y1.x,o3.y+y1.y,o3.z+y1.z,o3.w+y1.w);
                    }
                }
            }
            __syncthreads();
        }
        // epilogue (first 256 threads)
        if (tid < 256) {
            int row = tid >> 1;
            int uu0 = (tid & 1) * 4;
            int n = row;
            const float* Gp = g_G[d] + ((size_t)t_eff*N_ + n)*G4E_ + u0 + uu0;
            float4 Gi = *(const float4*)(Gp);
            float4 Gf = *(const float4*)(Gp + HE_);
            float4 Gc = *(const float4*)(Gp + 2*HE_);
            float4 Go = *(const float4*)(Gp + 3*HE_);
            float4 si = *(const float4*)&gs[row*36 + uu0];
            float4 sf = *(const float4*)&gs[row*36 + 8 + uu0];
            float4 sc = *(const float4*)&gs[row*36 + 16 + uu0];
            float4 so = *(const float4*)&gs[row*36 + 24 + uu0];
            float* cp = &g_ec[d][n*HE_ + u0 + uu0];
            float4 cv = (t > 0) ? *(const float4*)cp : make_float4(0.f,0.f,0.f,0.f);
            float4 cn, hn;
            cn.x = sigf(Gf.x+sf.x)*cv.x + sigf(Gi.x+si.x)*tanhf(Gc.x+sc.x);
            cn.y = sigf(Gf.y+sf.y)*cv.y + sigf(Gi.y+si.y)*tanhf(Gc.y+sc.y);
            cn.z = sigf(Gf.z+sf.z)*cv.z + sigf(Gi.z+si.z)*tanhf(Gc.z+sc.z);
            cn.w = sigf(Gf.w+sf.w)*cv.w + sigf(Gi.w+si.w)*tanhf(Gc.w+sc.w);
            hn.x = sigf(Go.x+so.x)*tanhf(cn.x);
            hn.y = sigf(Go.y+so.y)*tanhf(cn.y);
            hn.z = sigf(Go.z+so.z)*tanhf(cn.z);
            hn.w = sigf(Go.w+so.w)*tanhf(cn.w);
            *(float4*)cp = cn;
            *(float4*)&g_eh[1-(t&1)][d][n*HE_ + u0 + uu0] = hn;
            *(float4*)&obase[(size_t)t_eff*(N_*2*HE_) + (size_t)n*(2*HE_) + d*HE_ + u0 + uu0] = hn;
        }
        gridbar();
    }
}

// ---------------- decoder init ----------------
__global__ void k_dec_init()
{
    int i = blockIdx.x*blockDim.x + threadIdx.x;
    if (i < N_*HD_) {
        int n = i / HD_, k = i % HD_;
        g_dc[i] = g_enc[(size_t)n*(2*HE_) + HE_ + (k & (HE_-1))];
        g_dh[0][i] = 0.f;
    }
}

// ================= persistent decoder: 512 threads, K-split-8, 3-stage pipeline =================
__global__ __launch_bounds__(512) void k_decP(const float* __restrict__ dwhh,
        const float* __restrict__ db,
        const float* __restrict__ ow, const float* __restrict__ obv,
        const int* __restrict__ tags, float* __restrict__ out)
{
    extern __shared__ float sm[];
    float* Bs = sm;                        // [1024][36]
    float* As = sm + 1024*36;              // [3][32][132]
    float* gs = As + 3*32*132;             // [128][36]
    // logits overlay of As region:
    float* hsv = As;                       // [1024]
    float* lg  = As + 1024;                // [128]
    float* red = lg + 128;                 // [128]
    int*  redi = (int*)(red + 128);        // [128]

    const int b  = blockIdx.x;
    const int u0 = b * 8;
    const int tid = threadIdx.x;
    const int kg = tid >> 6;
    const int slot = tid & 63;
    const int r0 = (slot >> 2) * 8;
    const int c0 = (slot & 3) * 8;
    const int sr = tid & 127;
    const int sg = tid >> 7;

    for (int s = tid; s < 32*(HD_/4); s += 512) {
        int c = s / (HD_/4), k4 = s % (HD_/4);
        int wr = (c >> 3) * HD_ + u0 + (c & 7);
        float4 v = *(const float4*)(dwhh + (size_t)wr*HD_ + k4*4);
        Bs[(k4*4+0)*36 + c] = v.x;
        Bs[(k4*4+1)*36 + c] = v.y;
        Bs[(k4*4+2)*36 + c] = v.z;
        Bs[(k4*4+3)*36 + c] = v.w;
    }
    __syncthreads();

    for (int t = 0; t < L_; t++) {
        const int ph = t & 1;
        ull acc[4][8];
        #pragma unroll
        for (int p = 0; p < 4; p++)
            #pragma unroll
            for (int j = 0; j < 8; j++) acc[p][j] = 0ull;
        // ---- recurrent GEMM: A = h_prev + enc[t], 3-stage ----
        {
            const float* hin  = g_dh[ph];
            const float* encT = g_enc + (size_t)t * (N_*HD_);
            const float* hb0 = hin + (size_t)sr*HD_ + (2*sg)*128;
            const float* hb1 = hin + (size_t)sr*HD_ + (2*sg+1)*128;
            const float* eb0 = encT + (size_t)sr*HD_ + (2*sg)*128;
            const float* eb1 = encT + (size_t)sr*HD_ + (2*sg+1)*128;
            float4 h0, h1, e0, e1, ra0, ra1;
            // stage chunk 0
            h0 = __ldcg((const float4*)(hb0)); h1 = __ldcg((const float4*)(hb1));
            e0 = *(const float4*)(eb0);        e1 = *(const float4*)(eb1);
            ra0 = make_float4(h0.x+e0.x, h0.y+e0.y, h0.z+e0.z, h0.w+e0.w);
            ra1 = make_float4(h1.x+e1.x, h1.y+e1.y, h1.z+e1.z, h1.w+e1.w);
            {
                float* q0 = As + (8*sg)*132 + sr;
                float* q1 = As + (8*sg+4)*132 + sr;
                q0[0]=ra0.x; q0[132]=ra0.y; q0[264]=ra0.z; q0[396]=ra0.w;
                q1[0]=ra1.x; q1[132]=ra1.y; q1[264]=ra1.z; q1[396]=ra1.w;
            }
            // stage chunk 1
            h0 = __ldcg((const float4*)(hb0+4)); h1 = __ldcg((const float4*)(hb1+4));
            e0 = *(const float4*)(eb0+4);        e1 = *(const float4*)(eb1+4);
            ra0 = make_float4(h0.x+e0.x, h0.y+e0.y, h0.z+e0.z, h0.w+e0.w);
            ra1 = make_float4(h1.x+e1.x, h1.y+e1.y, h1.z+e1.z, h1.w+e1.w);
            {
                float* q0 = As + 4224 + (8*sg)*132 + sr;
                float* q1 = As + 4224 + (8*sg+4)*132 + sr;
                q0[0]=ra0.x; q0[132]=ra0.y; q0[264]=ra0.z; q0[396]=ra0.w;
                q1[0]=ra1.x; q1[132]=ra1.y; q1[264]=ra1.z; q1[396]=ra1.w;
            }
            __syncthreads();
            #pragma unroll 1
            for (int ch = 0; ch < 32; ch++) {
                if (ch + 2 < 32) {
                    h0 = __ldcg((const float4*)(hb0 + (ch+2)*4));
                    h1 = __ldcg((const float4*)(hb1 + (ch+2)*4));
                    e0 = *(const float4*)(eb0 + (ch+2)*4);
                    e1 = *(const float4*)(eb1 + (ch+2)*4);
                    ra0 = make_float4(h0.x+e0.x, h0.y+e0.y, h0.z+e0.z, h0.w+e0.w);
                    ra1 = make_float4(h1.x+e1.x, h1.y+e1.y, h1.z+e1.z, h1.w+e1.w);
                }
                int cb = ch % 3;
                const float* ap = As + cb*4224 + (kg*4)*132 + r0;
                const float* bp = Bs + (kg*128 + ch*4)*36 + c0;
                #pragma unroll
                for (int kk = 0; kk < 4; kk++) {
                    ulonglong2 aA = *(const ulonglong2*)(ap + kk*132);
                    ulonglong2 aB = *(const ulonglong2*)(ap + kk*132 + 4);
                    float4 b0 = *(const float4*)(bp + kk*36);
                    float4 b1 = *(const float4*)(bp + kk*36 + 4);
                    ull q[8] = {dup2(b0.x),dup2(b0.y),dup2(b0.z),dup2(b0.w),
                                dup2(b1.x),dup2(b1.y),dup2(b1.z),dup2(b1.w)};
                    ull ar[4] = {aA.x, aA.y, aB.x, aB.y};
                    #pragma unroll
                    for (int p = 0; p < 4; p++)
                        #pragma unroll
                        for (int j = 0; j < 8; j++)
                            fma2(acc[p][j], ar[p], q[j]);
                }
                if (ch + 2 < 32) {
                    int nb = (ch + 2) % 3;
                    float* q0 = As + nb*4224 + (8*sg)*132 + sr;
                    float* q1 = As + nb*4224 + (8*sg+4)*132 + sr;
                    q0[0]=ra0.x; q0[132]=ra0.y; q0[264]=ra0.z; q0[396]=ra0.w;
                    q1[0]=ra1.x; q1[132]=ra1.y; q1[264]=ra1.z; q1[396]=ra1.w;
                }
                __syncthreads();
            }
        }
        // reduce partials
        #pragma unroll 1
        for (int ph2 = 0; ph2 < 8; ph2++) {
            if (kg == ph2) {
                #pragma unroll
                for (int p = 0; p < 4; p++) {
                    float2 v[8];
                    #pragma unroll
                    for (int j = 0; j < 8; j++) v[j] = unpack2(acc[p][j]);
                    float* w0 = gs + (r0+2*p)*36 + c0;
                    float* w1 = gs + (r0+2*p+1)*36 + c0;
                    float4 x0 = make_float4(v[0].x,v[1].x,v[2].x,v[3].x);
                    float4 x1 = make_float4(v[4].x,v[5].x,v[6].x,v[7].x);
                    float4 y0 = make_float4(v[0].y,v[1].y,v[2].y,v[3].y);
                    float4 y1 = make_float4(v[4].y,v[5].y,v[6].y,v[7].y);
                    if (ph2 == 0) {
                        *(float4*)w0 = x0; *(float4*)(w0+4) = x1;
                        *(float4*)w1 = y0; *(float4*)(w1+4) = y1;
                    } else {
                        float4 o0 = *(const float4*)w0, o1 = *(const float4*)(w0+4);
                        float4 o2 = *(const float4*)w1, o3 = *(const float4*)(w1+4);
                        *(float4*)w0 = make_float4(o0.x+x0.x,o0.y+x0.y,o0.z+x0.z,o0.w+x0.w);
                        *(float4*)(w0+4) = make_float4(o1.x+x1.x,o1.y+x1.y,o1.z+x1.z,o1.w+x1.w);
                        *(float4*)w1 = make_float4(o2.x+y0.x,o2.y+y0.y,o2.z+y0.z,o2.w+y0.w);
                        *(float4*)(w1+4) = make_float4(o3.x+y1.x,o3.y+y1.y,o3.z+y1.z,o3.w+y1.w);
                    }
                }
            }
            __syncthreads();
        }
        // ---- epilogue (first 256 threads) ----
        if (tid < 256) {
            int row = tid >> 1;
            int uu0 = (tid & 1) * 4;
            int n = row;
            float4 si = *(const float4*)&gs[row*36 + uu0];
            float4 sf = *(const float4*)&gs[row*36 + 8 + uu0];
            float4 sc = *(const float4*)&gs[row*36 + 16 + uu0];
            float4 so = *(const float4*)&gs[row*36 + 24 + uu0];
            float4 bi = *(const float4*)(db + u0 + uu0);
            float4 bf = *(const float4*)(db + HD_ + u0 + uu0);
            float4 bc = *(const float4*)(db + 2*HD_ + u0 + uu0);
            float4 bo = *(const float4*)(db + 3*HD_ + u0 + uu0);
            float4 wi0 = make_float4(0.f,0.f,0.f,0.f), wi1 = wi0, wi2 = wi0, wi3 = wi0;
            if (t > 0) {
                int am = __ldcg(&g_amax[n]);
                const float* wr_ = g_wiT[am] + u0 + uu0;
                wi0 = *(const float4*)(wr_);
                wi1 = *(const float4*)(wr_ + HD_);
                wi2 = *(const float4*)(wr_ + 2*HD_);
                wi3 = *(const float4*)(wr_ + 3*HD_);
            }
            float gi[4] = {si.x+bi.x+wi0.x, si.y+bi.y+wi0.y, si.z+bi.z+wi0.z, si.w+bi.w+wi0.w};
            float gf[4] = {sf.x+bf.x+wi1.x, sf.y+bf.y+wi1.y, sf.z+bf.z+wi1.z, sf.w+bf.w+wi1.w};
            float gc[4] = {sc.x+bc.x+wi2.x, sc.y+bc.y+wi2.y, sc.z+bc.z+wi2.z, sc.w+bc.w+wi2.w};
            float go[4] = {so.x+bo.x+wi3.x, so.y+bo.y+wi3.y, so.z+bo.z+wi3.z, so.w+bo.w+wi3.w};
            float* cp = &g_dc[n*HD_ + u0 + uu0];
            float4 cv = *(const float4*)cp;
            float4 cn, hn;
            cn.x = sigf(gf[0])*cv.x + sigf(gi[0])*tanhf(gc[0]);
            cn.y = sigf(gf[1])*cv.y + sigf(gi[1])*tanhf(gc[1]);
            cn.z = sigf(gf[2])*cv.z + sigf(gi[2])*tanhf(gc[2]);
            cn.w = sigf(gf[3])*cv.w + sigf(gi[3])*tanhf(gc[3]);
            hn.x = sigf(go[0])*tanhf(cn.x);
            hn.y = sigf(go[1])*tanhf(cn.y);
            hn.z = sigf(go[2])*tanhf(cn.z);
            hn.w = sigf(go[3])*tanhf(cn.w);
            *(float4*)cp = cn;
            *(float4*)&g_dh[1-ph][n*HD_ + u0 + uu0] = hn;
        }
        gridbar();
        // ---- logits / softmax / argmax: block b = sample n, coalesced rows ----
        {
            const int n = b;
            const float* hsrc = g_dh[1-ph] + (size_t)n*HD_;
            for (int k = tid; k < HD_; k += 512) hsv[k] = __ldcg(hsrc + k);
            __syncthreads();
            {
                int w = tid >> 5, lane = tid & 31;
                #pragma unroll 1
                for (int rr = 0; rr < 8; rr++) {
                    int j = w*8 + rr;
                    const float* wrow = ow + (size_t)j*HD_ + lane*4;
                    const float* hh = hsv + lane*4;
                    ull s0 = 0ull, s1 = 0ull;
                    #pragma unroll
                    for (int i = 0; i < 8; i++) {
                        ulonglong2 wp = *(const ulonglong2*)(wrow + i*128);
                        ulonglong2 hp = *(const ulonglong2*)(hh + i*128);
                        fma2(s0, wp.x, hp.x);
                        fma2(s1, wp.y, hp.y);
                    }
                    float2 q0 = unpack2(s0), q1 = unpack2(s1);
                    float p = (q0.x + q0.y) + (q1.x + q1.y);
                    #pragma unroll
                    for (int off = 16; off > 0; off >>= 1)
                        p += __shfl_down_sync(0xffffffffu, p, off);
                    if (lane == 0) lg[j] = p + obv[j];
                }
            }
            __syncthreads();
            if (tid < 128) red[tid] = lg[tid];
            __syncthreads();
            for (int s = 64; s > 0; s >>= 1) { if (tid < s) red[tid] = fmaxf(red[tid], red[tid+s]); __syncthreads(); }
            float mx = red[0]; __syncthreads();
            float accv = 0.f, ev = 0.f;
            if (tid < 128) { accv = lg[tid]; ev = expf(accv - mx); red[tid] = ev; }
            __syncthreads();
            for (int s = 64; s > 0; s >>= 1) { if (tid < s) red[tid] += red[tid+s]; __syncthreads(); }
            float sum = red[0];
            if (tid < 128) out[((size_t)n*L_ + t)*T_ + tid] = ev / sum;
            int tag = tags[n*L_ + t];
            if (tid == tag) g_lterm[t*N_ + n] = -(accv - mx - logf(sum)) / (float)N_;
            __syncthreads();
            if (tid < 128) { red[tid] = lg[tid]; redi[tid] = tid; }
            __syncthreads();
            for (int s = 64; s > 0; s >>= 1) {
                if (tid < s) {
                    float o = red[tid+s]; int oi = redi[tid+s];
                    if (o > red[tid] || (o == red[tid] && oi < redi[tid])) { red[tid] = o; redi[tid] = oi; }
                }
                __syncthreads();
            }
            if (tid == 0) g_amax[n] = redi[0];
        }
        gridbar();
    }
}

// ---------------- deterministic loss reduction ----------------
__global__ void k_loss(float* __restrict__ out)
{
    __shared__ float red[256];
    float s = 0.f;
    for (int i = threadIdx.x; i < L_*N_; i += 256) s += g_lterm[i];
    red[threadIdx.x] = s; __syncthreads();
    for (int st = 128; st > 0; st >>= 1) {
        if (threadIdx.x < st) red[threadIdx.x] += red[threadIdx.x + st];
        __syncthreads();
    }
    if (threadIdx.x == 0) out[(size_t)N_*L_*T_] = red[0];
}

// ---------------- launcher ----------------
#define ENC_SMEM ((512*36 + 3*32*132 + 128*36)*4)
#define DEC_SMEM ((1024*36 + 3*32*132 + 128*36)*4)

extern "C" void kernel_launch(void* const* d_in, const int* in_sizes, int n_in,
                              void* d_out, int out_size)
{
    const int*   ids    = (const int*)  d_in[0];
    const int*   tags   = (const int*)  d_in[1];
    const float* embed  = (const float*)d_in[2];
    const float* e0_wih = (const float*)d_in[3];
    const float* e0_whh = (const float*)d_in[4];
    const float* e0_b   = (const float*)d_in[5];
    const float* e1_wih = (const float*)d_in[6];
    const float* e1_whh = (const float*)d_in[7];
    const float* e1_b   = (const float*)d_in[8];
    const float* dwih   = (const float*)d_in[9];
    const float* dwhh   = (const float*)d_in[10];
    const float* db     = (const float*)d_in[11];
    const float* ow     = (const float*)d_in[12];
    const float* obv    = (const float*)d_in[13];
    float* out = (float*)d_out;

    cudaFuncSetAttribute(k_encP, cudaFuncAttributeMaxDynamicSharedMemorySize, ENC_SMEM);
    cudaFuncSetAttribute(k_decP, cudaFuncAttributeMaxDynamicSharedMemorySize, DEC_SMEM);

    // 1. embedding + dwih transpose
    k_embed<<<(LN_*E_/4 + 255)/256, 256>>>(ids, embed);
    k_wiT<<<(4*HD_*T_ + 255)/256, 256>>>(dwih);

    // 2. enc0
    {
        dim3 gg(G4E_/128, LN_/128, 2);
        k_gemm_bias<<<gg, 256>>>(0, e0_wih, e0_b, E_);
    }
    k_encP<<<NB_, 512, ENC_SMEM>>>(0, e0_whh);

    // 3. enc1
    {
        dim3 gg(G4E_/128, LN_/128, 2);
        k_gemm_bias<<<gg, 256>>>(1, e1_wih, e1_b, 2*HE_);
    }
    k_encP<<<NB_, 512, ENC_SMEM>>>(1, e1_whh);

    // 4. decoder
    k_dec_init<<<(N_*HD_ + 255)/256, 256>>>();
    k_decP<<<NB_, 512, DEC_SMEM>>>(dwhh, db, ow, obv, tags, out);

    // 5. loss
    k_loss<<<1, 256>>>(out);
}

// round 12
// speedup vs baseline: 1.1257x; 1.1257x over previous
#include <cuda_runtime.h>

typedef unsigned long long ull;

#define N_ 128
#define L_ 160
#define E_ 512
#define HE_ 512
#define HD_ 1024
#define T_ 128
#define LN_ (L_*N_)
#define G4E_ 2048
#define NB_ 128u

// ---------------- scratch (device globals) ----------------
__device__ __align__(16) float g_xs[LN_*E_];
__device__ __align__(16) float g_G[2][(size_t)LN_*G4E_];
__device__ __align__(16) float g_h1[(size_t)LN_*2*HE_];
__device__ __align__(16) float g_enc[(size_t)LN_*2*HE_];
__device__ __align__(16) float g_eh[2][2][N_*HE_];   // [phase][dir]
__device__ __align__(16) float g_ec[2][N_*HE_];      // [dir]
__device__ __align__(16) float g_dh[2][N_*HD_];
__device__ __align__(16) float g_dc[N_*HD_];
__device__ __align__(16) float g_wiT[T_][4*HD_];     // transposed dec_wih (2MB)
__device__ int   g_amax[N_];
__device__ float g_lterm[L_*N_];

__device__ unsigned g_bcnt = 0;
__device__ volatile unsigned g_bgen = 0;

__device__ __forceinline__ void fma2(ull& d, ull a, ull b){
    asm("fma.rn.f32x2 %0, %1, %2, %0;" : "+l"(d) : "l"(a), "l"(b));
}
__device__ __forceinline__ ull dup2(float x){
    ull r; asm("mov.b64 %0, {%1, %1};" : "=l"(r) : "f"(x)); return r;
}
__device__ __forceinline__ float2 unpack2(ull v){
    float2 r; asm("mov.b64 {%0, %1}, %2;" : "=f"(r.x), "=f"(r.y) : "l"(v)); return r;
}
__device__ __forceinline__ float sigf(float x){ return 1.f/(1.f+expf(-x)); }

__device__ __forceinline__ void gridbar(){
    __syncthreads();
    if (threadIdx.x == 0) {
        unsigned g = g_bgen;
        __threadfence();
        if (atomicAdd(&g_bcnt, 1u) == NB_ - 1u) {
            atomicExch(&g_bcnt, 0u);
            __threadfence();
            g_bgen = g + 1u;
        } else {
            while (g_bgen == g) { }
        }
        __threadfence();
    }
    __syncthreads();
}

// ---------------- embedding ----------------
__global__ void k_embed(const int* __restrict__ ids, const float* __restrict__ embed)
{
    int i = blockIdx.x*blockDim.x + threadIdx.x;
    const int tot = LN_*E_/4;
    if (i >= tot) return;
    int e4 = i % (E_/4);
    int ln = i / (E_/4);
    int l = ln / N_, n = ln % N_;
    int id = ids[n*L_ + l];
    reinterpret_cast<float4*>(g_xs)[i] =
        reinterpret_cast<const float4*>(embed + (size_t)id*E_)[e4];
}

// ---------------- dwih transpose: g_wiT[idx][col] = dwih[col*T + idx] ----------------
__global__ void k_wiT(const float* __restrict__ dwih)
{
    int i = blockIdx.x*blockDim.x + threadIdx.x;
    if (i < 4*HD_*T_) {
        int col = i >> 7;
        int idx = i & 127;
        g_wiT[idx][col] = dwih[i];
    }
}

// ---------------- big input GEMM (R9/R10 version, fma 66%) ----------------
__global__ __launch_bounds__(256) void k_gemm_bias(int asel, const float* __restrict__ Ball,
                                                   const float* __restrict__ biasall, int K)
{
    const float* A = asel ? g_h1 : g_xs;
    int z = blockIdx.z;
    const float* B = Ball + (size_t)z * G4E_ * K;
    const float* bias = biasall + z * G4E_;
    float* C = g_G[z];
    int m0 = blockIdx.y * 128, n0 = blockIdx.x * 128;
    __shared__ float As[8][132];
    __shared__ float Bs[8][132];
    int tid = threadIdx.x;
    int lr = tid >> 1, lk = (tid & 1) * 4;
    int ry = (tid >> 4) * 8;
    int c4 = (tid & 15) * 4;
    ull acc[4][8];
    #pragma unroll
    for (int p = 0; p < 4; p++)
        #pragma unroll
        for (int j = 0; j < 8; j++) acc[p][j] = 0ull;
    const float* Arow = A + (size_t)(m0+lr)*K + lk;
    const float* Brow = B + (size_t)(n0+lr)*K + lk;
    #pragma unroll 1
    for (int kc = 0; kc < K; kc += 8) {
        float4 av = *(const float4*)(Arow + kc);
        float4 bv = *(const float4*)(Brow + kc);
        __syncthreads();
        As[lk+0][lr]=av.x; As[lk+1][lr]=av.y; As[lk+2][lr]=av.z; As[lk+3][lr]=av.w;
        Bs[lk+0][lr]=bv.x; Bs[lk+1][lr]=bv.y; Bs[lk+2][lr]=bv.z; Bs[lk+3][lr]=bv.w;
        __syncthreads();
        #pragma unroll
        for (int kk = 0; kk < 8; kk++) {
            ulonglong2 aA = *(const ulonglong2*)&As[kk][ry];
            ulonglong2 aB = *(const ulonglong2*)&As[kk][ry+4];
            float4 b0 = *(const float4*)&Bs[kk][c4];
            float4 b1 = *(const float4*)&Bs[kk][64+c4];
            ull q[8] = {dup2(b0.x),dup2(b0.y),dup2(b0.z),dup2(b0.w),
                        dup2(b1.x),dup2(b1.y),dup2(b1.z),dup2(b1.w)};
            ull ar[4] = {aA.x, aA.y, aB.x, aB.y};
            #pragma unroll
            for (int p = 0; p < 4; p++)
                #pragma unroll
                for (int j = 0; j < 8; j++)
                    fma2(acc[p][j], ar[p], q[j]);
        }
    }
    float4 bia0 = *(const float4*)(bias + n0 + c4);
    float4 bia1 = *(const float4*)(bias + n0 + 64 + c4);
    #pragma unroll
    for (int p = 0; p < 4; p++) {
        float2 v[8];
        #pragma unroll
        for (int j = 0; j < 8; j++) v[j] = unpack2(acc[p][j]);
        float* C0 = C + (size_t)(m0+ry+2*p)*G4E_ + n0;
        float* C1 = C + (size_t)(m0+ry+2*p+1)*G4E_ + n0;
        *(float4*)(C0 + c4)    = make_float4(v[0].x+bia0.x, v[1].x+bia0.y, v[2].x+bia0.z, v[3].x+bia0.w);
        *(float4*)(C0 + 64+c4) = make_float4(v[4].x+bia1.x, v[5].x+bia1.y, v[6].x+bia1.z, v[7].x+bia1.w);
        *(float4*)(C1 + c4)    = make_float4(v[0].y+bia0.x, v[1].y+bia0.y, v[2].y+bia0.z, v[3].y+bia0.w);
        *(float4*)(C1 + 64+c4) = make_float4(v[4].y+bia1.x, v[5].y+bia1.y, v[6].y+bia1.z, v[7].y+bia1.w);
    }
}

// ================= persistent encoder: 512 threads, K-split-8 (R10 structure) =================
__global__ __launch_bounds__(512) void k_encP(int layer, const float* __restrict__ whh_all)
{
    extern __shared__ float sm[];
    float* Bs = sm;                        // [512][36]
    float* As = sm + 512*36;               // [2][32][132]
    float* gs = As + 2*32*132;             // [128][36]

    const int b  = blockIdx.x;
    const int d  = b >> 6;
    const int u0 = (b & 63) * 8;
    const int tid = threadIdx.x;
    const int kg = tid >> 6;               // K-group 0..7
    const int slot = tid & 63;
    const int r0 = (slot >> 2) * 8;
    const int c0 = (slot & 3) * 8;
    const int sr = tid & 127;              // stage row
    const int sg = tid >> 7;               // stage group 0..3 -> kg pair (2sg,2sg+1)

    {
        const float* wb = whh_all + (size_t)d * (4*HE_) * HE_;
        for (int s = tid; s < 32*(HE_/4); s += 512) {
            int c = s / (HE_/4), k4 = s % (HE_/4);
            int wr = (c >> 3) * HE_ + u0 + (c & 7);
            float4 v = *(const float4*)(wb + (size_t)wr*HE_ + k4*4);
            Bs[(k4*4+0)*36 + c] = v.x;
            Bs[(k4*4+1)*36 + c] = v.y;
            Bs[(k4*4+2)*36 + c] = v.z;
            Bs[(k4*4+3)*36 + c] = v.w;
        }
    }
    float* obase = layer ? g_enc : g_h1;
    __syncthreads();

    for (int t = 0; t < L_; t++) {
        const int t_eff = d ? (L_-1-t) : t;
        ull acc[4][8];
        #pragma unroll
        for (int p = 0; p < 4; p++)
            #pragma unroll
            for (int j = 0; j < 8; j++) acc[p][j] = 0ull;

        if (t > 0) {
            const float* hin = g_eh[t & 1][d];
            const size_t sb = (size_t)sr*HE_;
            float4 ra0 = __ldcg((const float4*)(hin + sb + (2*sg)*64));
            float4 ra1 = __ldcg((const float4*)(hin + sb + (2*sg+1)*64));
            {
                float* q0 = As + (8*sg)*132 + sr;
                float* q1 = As + (8*sg+4)*132 + sr;
                q0[0]=ra0.x; q0[132]=ra0.y; q0[264]=ra0.z; q0[396]=ra0.w;
                q1[0]=ra1.x; q1[132]=ra1.y; q1[264]=ra1.z; q1[396]=ra1.w;
            }
            __syncthreads();
            int buf = 0;
            #pragma unroll 1
            for (int ch = 0; ch < 16; ch++) {
                if (ch + 1 < 16) {
                    ra0 = __ldcg((const float4*)(hin + sb + (2*sg)*64 + (ch+1)*4));
                    ra1 = __ldcg((const float4*)(hin + sb + (2*sg+1)*64 + (ch+1)*4));
                }
                const float* ap = As + buf*4224 + (kg*4)*132 + r0;
                const float* bp = Bs + (kg*64 + ch*4)*36 + c0;
                #pragma unroll
                for (int kk = 0; kk < 4; kk++) {
                    ulonglong2 aA = *(const ulonglong2*)(ap + kk*132);
                    ulonglong2 aB = *(const ulonglong2*)(ap + kk*132 + 4);
                    float4 b0 = *(const float4*)(bp + kk*36);
                    float4 b1 = *(const float4*)(bp + kk*36 + 4);
                    ull q[8] = {dup2(b0.x),dup2(b0.y),dup2(b0.z),dup2(b0.w),
                                dup2(b1.x),dup2(b1.y),dup2(b1.z),dup2(b1.w)};
                    ull ar[4] = {aA.x, aA.y, aB.x, aB.y};
                    #pragma unroll
                    for (int p = 0; p < 4; p++)
                        #pragma unroll
                        for (int j = 0; j < 8; j++)
                            fma2(acc[p][j], ar[p], q[j]);
                }
                if (ch + 1 < 16) {
                    int nb = buf ^ 1;
                    float* q0 = As + nb*4224 + (8*sg)*132 + sr;
                    float* q1 = As + nb*4224 + (8*sg+4)*132 + sr;
                    q0[0]=ra0.x; q0[132]=ra0.y; q0[264]=ra0.z; q0[396]=ra0.w;
                    q1[0]=ra1.x; q1[132]=ra1.y; q1[264]=ra1.z; q1[396]=ra1.w;
                    __syncthreads();
                    buf = nb;
                }
            }
        }
        // reduce 8 K-group partials into gs
        #pragma unroll 1
        for (int ph2 = 0; ph2 < 8; ph2++) {
            if (kg == ph2) {
                #pragma unroll
                for (int p = 0; p < 4; p++) {
                    float2 v[8];
                    #pragma unroll
                    for (int j = 0; j < 8; j++) v[j] = unpack2(acc[p][j]);
                    float* w0 = gs + (r0+2*p)*36 + c0;
                    float* w1 = gs + (r0+2*p+1)*36 + c0;
                    float4 x0 = make_float4(v[0].x,v[1].x,v[2].x,v[3].x);
                    float4 x1 = make_float4(v[4].x,v[5].x,v[6].x,v[7].x);
                    float4 y0 = make_float4(v[0].y,v[1].y,v[2].y,v[3].y);
                    float4 y1 = make_float4(v[4].y,v[5].y,v[6].y,v[7].y);
                    if (ph2 == 0) {
                        *(float4*)w0 = x0; *(float4*)(w0+4) = x1;
                        *(float4*)w1 = y0; *(float4*)(w1+4) = y1;
                    } else {
                        float4 o0 = *(const float4*)w0, o1 = *(const float4*)(w0+4);
                        float4 o2 = *(const float4*)w1, o3 = *(const float4*)(w1+4);
                        *(float4*)w0 = make_float4(o0.x+x0.x,o0.y+x0.y,o0.z+x0.z,o0.w+x0.w);
                        *(float4*)(w0+4) = make_float4(o1.x+x1.x,o1.y+x1.y,o1.z+x1.z,o1.w+x1.w);
                        *(float4*)w1 = make_float4(o2.x+y0.x,o2.y+y0.y,o2.z+y0.z,o2.w+y0.w);
                        *(float4*)(w1+4) = make_float4(o3.x+y1.x,o3.y+y1.y,o3.z+y1.z,o3.w+y1.w);
                    }
                }
            }
            __syncthreads();
        }
        // epilogue (first 256 threads)
        if (tid < 256) {
            int row = tid >> 1;
            int uu0 = (tid & 1) * 4;
            int n = row;
            const float* Gp = g_G[d] + ((size_t)t_eff*N_ + n)*G4E_ + u0 + uu0;
            float4 Gi = *(const float4*)(Gp);
            float4 Gf = *(const float4*)(Gp + HE_);
            float4 Gc = *(const float4*)(Gp + 2*HE_);
            float4 Go = *(const float4*)(Gp + 3*HE_);
            float4 si = *(const float4*)&gs[row*36 + uu0];
            float4 sf = *(const float4*)&gs[row*36 + 8 + uu0];
            float4 sc = *(const float4*)&gs[row*36 + 16 + uu0];
            float4 so = *(const float4*)&gs[row*36 + 24 + uu0];
            float* cp = &g_ec[d][n*HE_ + u0 + uu0];
            float4 cv = (t > 0) ? *(const float4*)cp : make_float4(0.f,0.f,0.f,0.f);
            float4 cn, hn;
            cn.x = sigf(Gf.x+sf.x)*cv.x + sigf(Gi.x+si.x)*tanhf(Gc.x+sc.x);
            cn.y = sigf(Gf.y+sf.y)*cv.y + sigf(Gi.y+si.y)*tanhf(Gc.y+sc.y);
            cn.z = sigf(Gf.z+sf.z)*cv.z + sigf(Gi.z+si.z)*tanhf(Gc.z+sc.z);
            cn.w = sigf(Gf.w+sf.w)*cv.w + sigf(Gi.w+si.w)*tanhf(Gc.w+sc.w);
            hn.x = sigf(Go.x+so.x)*tanhf(cn.x);
            hn.y = sigf(Go.y+so.y)*tanhf(cn.y);
            hn.z = sigf(Go.z+so.z)*tanhf(cn.z);
            hn.w = sigf(Go.w+so.w)*tanhf(cn.w);
            *(float4*)cp = cn;
            *(float4*)&g_eh[1-(t&1)][d][n*HE_ + u0 + uu0] = hn;
            *(float4*)&obase[(size_t)t_eff*(N_*2*HE_) + (size_t)n*(2*HE_) + d*HE_ + u0 + uu0] = hn;
        }
        gridbar();
    }
}

// ---------------- decoder init ----------------
__global__ void k_dec_init()
{
    int i = blockIdx.x*blockDim.x + threadIdx.x;
    if (i < N_*HD_) {
        int n = i / HD_, k = i % HD_;
        g_dc[i] = g_enc[(size_t)n*(2*HE_) + HE_ + (k & (HE_-1))];
        g_dh[0][i] = 0.f;
    }
}

// ================= persistent decoder: 512 threads, K-split-8 (R10 structure, wiT epilogue) =================
__global__ __launch_bounds__(512) void k_decP(const float* __restrict__ dwhh,
        const float* __restrict__ db,
        const float* __restrict__ ow, const float* __restrict__ obv,
        const int* __restrict__ tags, float* __restrict__ out)
{
    extern __shared__ float sm[];
    float* Bs = sm;                        // [1024][36]
    float* As = sm + 1024*36;              // [2][32][132]
    float* gs = As + 2*32*132;             // [128][36]
    // logits overlay of As region:
    float* hsv = As;                       // [1024]
    float* lg  = As + 1024;                // [128]
    float* red = lg + 128;                 // [128]
    int*  redi = (int*)(red + 128);        // [128]

    const int b  = blockIdx.x;
    const int u0 = b * 8;
    const int tid = threadIdx.x;
    const int kg = tid >> 6;
    const int slot = tid & 63;
    const int r0 = (slot >> 2) * 8;
    const int c0 = (slot & 3) * 8;
    const int sr = tid & 127;
    const int sg = tid >> 7;

    for (int s = tid; s < 32*(HD_/4); s += 512) {
        int c = s / (HD_/4), k4 = s % (HD_/4);
        int wr = (c >> 3) * HD_ + u0 + (c & 7);
        float4 v = *(const float4*)(dwhh + (size_t)wr*HD_ + k4*4);
        Bs[(k4*4+0)*36 + c] = v.x;
        Bs[(k4*4+1)*36 + c] = v.y;
        Bs[(k4*4+2)*36 + c] = v.z;
        Bs[(k4*4+3)*36 + c] = v.w;
    }
    __syncthreads();

    for (int t = 0; t < L_; t++) {
        const int ph = t & 1;
        ull acc[4][8];
        #pragma unroll
        for (int p = 0; p < 4; p++)
            #pragma unroll
            for (int j = 0; j < 8; j++) acc[p][j] = 0ull;
        // ---- recurrent GEMM: A = h_prev + enc[t] ----
        {
            const float* hin  = g_dh[ph];
            const float* encT = g_enc + (size_t)t * (N_*HD_);
            const size_t sb = (size_t)sr*HD_;
            float4 h0 = __ldcg((const float4*)(hin + sb + (2*sg)*128));
            float4 h1 = __ldcg((const float4*)(hin + sb + (2*sg+1)*128));
            float4 e0 = *(const float4*)(encT + sb + (2*sg)*128);
            float4 e1 = *(const float4*)(encT + sb + (2*sg+1)*128);
            float4 ra0 = make_float4(h0.x+e0.x, h0.y+e0.y, h0.z+e0.z, h0.w+e0.w);
            float4 ra1 = make_float4(h1.x+e1.x, h1.y+e1.y, h1.z+e1.z, h1.w+e1.w);
            {
                float* q0 = As + (8*sg)*132 + sr;
                float* q1 = As + (8*sg+4)*132 + sr;
                q0[0]=ra0.x; q0[132]=ra0.y; q0[264]=ra0.z; q0[396]=ra0.w;
                q1[0]=ra1.x; q1[132]=ra1.y; q1[264]=ra1.z; q1[396]=ra1.w;
            }
            __syncthreads();
            int buf = 0;
            #pragma unroll 1
            for (int ch = 0; ch < 32; ch++) {
                if (ch + 1 < 32) {
                    h0 = __ldcg((const float4*)(hin + sb + (2*sg)*128 + (ch+1)*4));
                    h1 = __ldcg((const float4*)(hin + sb + (2*sg+1)*128 + (ch+1)*4));
                    e0 = *(const float4*)(encT + sb + (2*sg)*128 + (ch+1)*4);
                    e1 = *(const float4*)(encT + sb + (2*sg+1)*128 + (ch+1)*4);
                    ra0 = make_float4(h0.x+e0.x, h0.y+e0.y, h0.z+e0.z, h0.w+e0.w);
                    ra1 = make_float4(h1.x+e1.x, h1.y+e1.y, h1.z+e1.z, h1.w+e1.w);
                }
                const float* ap = As + buf*4224 + (kg*4)*132 + r0;
                const float* bp = Bs + (kg*128 + ch*4)*36 + c0;
                #pragma unroll
                for (int kk = 0; kk < 4; kk++) {
                    ulonglong2 aA = *(const ulonglong2*)(ap + kk*132);
                    ulonglong2 aB = *(const ulonglong2*)(ap + kk*132 + 4);
                    float4 b0 = *(const float4*)(bp + kk*36);
                    float4 b1 = *(const float4*)(bp + kk*36 + 4);
                    ull q[8] = {dup2(b0.x),dup2(b0.y),dup2(b0.z),dup2(b0.w),
                                dup2(b1.x),dup2(b1.y),dup2(b1.z),dup2(b1.w)};
                    ull ar[4] = {aA.x, aA.y, aB.x, aB.y};
                    #pragma unroll
                    for (int p = 0; p < 4; p++)
                        #pragma unroll
                        for (int j = 0; j < 8; j++)
                            fma2(acc[p][j], ar[p], q[j]);
                }
                if (ch + 1 < 32) {
                    int nb = buf ^ 1;
                    float* q0 = As + nb*4224 + (8*sg)*132 + sr;
                    float* q1 = As + nb*4224 + (8*sg+4)*132 + sr;
                    q0[0]=ra0.x; q0[132]=ra0.y; q0[264]=ra0.z; q0[396]=ra0.w;
                    q1[0]=ra1.x; q1[132]=ra1.y; q1[264]=ra1.z; q1[396]=ra1.w;
                    __syncthreads();
                    buf = nb;
                }
            }
        }
        // reduce partials
        #pragma unroll 1
        for (int ph2 = 0; ph2 < 8; ph2++) {
            if (kg == ph2) {
                #pragma unroll
                for (int p = 0; p < 4; p++) {
                    float2 v[8];
                    #pragma unroll
                    for (int j = 0; j < 8; j++) v[j] = unpack2(acc[p][j]);
                    float* w0 = gs + (r0+2*p)*36 + c0;
                    float* w1 = gs + (r0+2*p+1)*36 + c0;
                    float4 x0 = make_float4(v[0].x,v[1].x,v[2].x,v[3].x);
                    float4 x1 = make_float4(v[4].x,v[5].x,v[6].x,v[7].x);
                    float4 y0 = make_float4(v[0].y,v[1].y,v[2].y,v[3].y);
                    float4 y1 = make_float4(v[4].y,v[5].y,v[6].y,v[7].y);
                    if (ph2 == 0) {
                        *(float4*)w0 = x0; *(float4*)(w0+4) = x1;
                        *(float4*)w1 = y0; *(float4*)(w1+4) = y1;
                    } else {
                        float4 o0 = *(const float4*)w0, o1 = *(const float4*)(w0+4);
                        float4 o2 = *(const float4*)w1, o3 = *(const float4*)(w1+4);
                        *(float4*)w0 = make_float4(o0.x+x0.x,o0.y+x0.y,o0.z+x0.z,o0.w+x0.w);
                        *(float4*)(w0+4) = make_float4(o1.x+x1.x,o1.y+x1.y,o1.z+x1.z,o1.w+x1.w);
                        *(float4*)w1 = make_float4(o2.x+y0.x,o2.y+y0.y,o2.z+y0.z,o2.w+y0.w);
                        *(float4*)(w1+4) = make_float4(o3.x+y1.x,o3.y+y1.y,o3.z+y1.z,o3.w+y1.w);
                    }
                }
            }
            __syncthreads();
        }
        // ---- epilogue (first 256 threads), coalesced g_wiT reads ----
        if (tid < 256) {
            int row = tid >> 1;
            int uu0 = (tid & 1) * 4;
            int n = row;
            float4 si = *(const float4*)&gs[row*36 + uu0];
            float4 sf = *(const float4*)&gs[row*36 + 8 + uu0];
            float4 sc = *(const float4*)&gs[row*36 + 16 + uu0];
            float4 so = *(const float4*)&gs[row*36 + 24 + uu0];
            float4 bi = *(const float4*)(db + u0 + uu0);
            float4 bf = *(const float4*)(db + HD_ + u0 + uu0);
            float4 bc = *(const float4*)(db + 2*HD_ + u0 + uu0);
            float4 bo = *(const float4*)(db + 3*HD_ + u0 + uu0);
            float4 wi0 = make_float4(0.f,0.f,0.f,0.f), wi1 = wi0, wi2 = wi0, wi3 = wi0;
            if (t > 0) {
                int am = __ldcg(&g_amax[n]);
                const float* wr_ = g_wiT[am] + u0 + uu0;
                wi0 = *(const float4*)(wr_);
                wi1 = *(const float4*)(wr_ + HD_);
                wi2 = *(const float4*)(wr_ + 2*HD_);
                wi3 = *(const float4*)(wr_ + 3*HD_);
            }
            float gi[4] = {si.x+bi.x+wi0.x, si.y+bi.y+wi0.y, si.z+bi.z+wi0.z, si.w+bi.w+wi0.w};
            float gf[4] = {sf.x+bf.x+wi1.x, sf.y+bf.y+wi1.y, sf.z+bf.z+wi1.z, sf.w+bf.w+wi1.w};
            float gc[4] = {sc.x+bc.x+wi2.x, sc.y+bc.y+wi2.y, sc.z+bc.z+wi2.z, sc.w+bc.w+wi2.w};
            float go[4] = {so.x+bo.x+wi3.x, so.y+bo.y+wi3.y, so.z+bo.z+wi3.z, so.w+bo.w+wi3.w};
            float* cp = &g_dc[n*HD_ + u0 + uu0];
            float4 cv = *(const float4*)cp;
            float4 cn, hn;
            cn.x = sigf(gf[0])*cv.x + sigf(gi[0])*tanhf(gc[0]);
            cn.y = sigf(gf[1])*cv.y + sigf(gi[1])*tanhf(gc[1]);
            cn.z = sigf(gf[2])*cv.z + sigf(gi[2])*tanhf(gc[2]);
            cn.w = sigf(gf[3])*cv.w + sigf(gi[3])*tanhf(gc[3]);
            hn.x = sigf(go[0])*tanhf(cn.x);
            hn.y = sigf(go[1])*tanhf(cn.y);
            hn.z = sigf(go[2])*tanhf(cn.z);
            hn.w = sigf(go[3])*tanhf(cn.w);
            *(float4*)cp = cn;
            *(float4*)&g_dh[1-ph][n*HD_ + u0 + uu0] = hn;
        }
        gridbar();
        // ---- logits / softmax / argmax: block b = sample n, coalesced rows ----
        {
            const int n = b;
            const float* hsrc = g_dh[1-ph] + (size_t)n*HD_;
            for (int k = tid; k < HD_; k += 512) hsv[k] = __ldcg(hsrc + k);
            __syncthreads();
            {
                int w = tid >> 5, lane = tid & 31;
                #pragma unroll 1
                for (int rr = 0; rr < 8; rr++) {
                    int j = w*8 + rr;
                    const float* wrow = ow + (size_t)j*HD_ + lane*4;
                    const float* hh = hsv + lane*4;
                    ull s0 = 0ull, s1 = 0ull;
                    #pragma unroll
                    for (int i = 0; i < 8; i++) {
                        ulonglong2 wp = *(const ulonglong2*)(wrow + i*128);
                        ulonglong2 hp = *(const ulonglong2*)(hh + i*128);
                        fma2(s0, wp.x, hp.x);
                        fma2(s1, wp.y, hp.y);
                    }
                    float2 q0 = unpack2(s0), q1 = unpack2(s1);
                    float p = (q0.x + q0.y) + (q1.x + q1.y);
                    #pragma unroll
                    for (int off = 16; off > 0; off >>= 1)
                        p += __shfl_down_sync(0xffffffffu, p, off);
                    if (lane == 0) lg[j] = p + obv[j];
                }
            }
            __syncthreads();
            if (tid < 128) red[tid] = lg[tid];
            __syncthreads();
            for (int s = 64; s > 0; s >>= 1) { if (tid < s) red[tid] = fmaxf(red[tid], red[tid+s]); __syncthreads(); }
            float mx = red[0]; __syncthreads();
            float accv = 0.f, ev = 0.f;
            if (tid < 128) { accv = lg[tid]; ev = expf(accv - mx); red[tid] = ev; }
            __syncthreads();
            for (int s = 64; s > 0; s >>= 1) { if (tid < s) red[tid] += red[tid+s]; __syncthreads(); }
            float sum = red[0];
            if (tid < 128) out[((size_t)n*L_ + t)*T_ + tid] = ev / sum;
            int tag = tags[n*L_ + t];
            if (tid == tag) g_lterm[t*N_ + n] = -(accv - mx - logf(sum)) / (float)N_;
            __syncthreads();
            if (tid < 128) { red[tid] = lg[tid]; redi[tid] = tid; }
            __syncthreads();
            for (int s = 64; s > 0; s >>= 1) {
                if (tid < s) {
                    float o = red[tid+s]; int oi = redi[tid+s];
                    if (o > red[tid] || (o == red[tid] && oi < redi[tid])) { red[tid] = o; redi[tid] = oi; }
                }
                __syncthreads();
            }
            if (tid == 0) g_amax[n] = redi[0];
        }
        gridbar();
    }
}

// ---------------- deterministic loss reduction ----------------
__global__ void k_loss(float* __restrict__ out)
{
    __shared__ float red[256];
    float s = 0.f;
    for (int i = threadIdx.x; i < L_*N_; i += 256) s += g_lterm[i];
    red[threadIdx.x] = s; __syncthreads();
    for (int st = 128; st > 0; st >>= 1) {
        if (threadIdx.x < st) red[threadIdx.x] += red[threadIdx.x + st];
        __syncthreads();
    }
    if (threadIdx.x == 0) out[(size_t)N_*L_*T_] = red[0];
}

// ---------------- launcher ----------------
#define ENC_SMEM ((512*36 + 2*32*132 + 128*36)*4)
#define DEC_SMEM ((1024*36 + 2*32*132 + 128*36)*4)

extern "C" void kernel_launch(void* const* d_in, const int* in_sizes, int n_in,
                              void* d_out, int out_size)
{
    const int*   ids    = (const int*)  d_in[0];
    const int*   tags   = (const int*)  d_in[1];
    const float* embed  = (const float*)d_in[2];
    const float* e0_wih = (const float*)d_in[3];
    const float* e0_whh = (const float*)d_in[4];
    const float* e0_b   = (const float*)d_in[5];
    const float* e1_wih = (const float*)d_in[6];
    const float* e1_whh = (const float*)d_in[7];
    const float* e1_b   = (const float*)d_in[8];
    const float* dwih   = (const float*)d_in[9];
    const float* dwhh   = (const float*)d_in[10];
    const float* db     = (const float*)d_in[11];
    const float* ow     = (const float*)d_in[12];
    const float* obv    = (const float*)d_in[13];
    float* out = (float*)d_out;

    cudaFuncSetAttribute(k_encP, cudaFuncAttributeMaxDynamicSharedMemorySize, ENC_SMEM);
    cudaFuncSetAttribute(k_decP, cudaFuncAttributeMaxDynamicSharedMemorySize, DEC_SMEM);

    // 1. embedding + dwih transpose
    k_embed<<<(LN_*E_/4 + 255)/256, 256>>>(ids, embed);
    k_wiT<<<(4*HD_*T_ + 255)/256, 256>>>(dwih);

    // 2. enc0
    {
        dim3 gg(G4E_/128, LN_/128, 2);
        k_gemm_bias<<<gg, 256>>>(0, e0_wih, e0_b, E_);
    }
    k_encP<<<NB_, 512, ENC_SMEM>>>(0, e0_whh);

    // 3. enc1
    {
        dim3 gg(G4E_/128, LN_/128, 2);
        k_gemm_bias<<<gg, 256>>>(1, e1_wih, e1_b, 2*HE_);
    }
    k_encP<<<NB_, 512, ENC_SMEM>>>(1, e1_whh);

    // 4. decoder
    k_dec_init<<<(N_*HD_ + 255)/256, 256>>>();
    k_decP<<<NB_, 512, DEC_SMEM>>>(dwhh, db, ow, obv, tags, out);

    // 5. loss
    k_loss<<<1, 256>>>(out);
}

// round 13
// speedup vs baseline: 1.2279x; 1.0908x over previous
#include <cuda_runtime.h>

typedef unsigned long long ull;

#define N_ 128
#define L_ 160
#define E_ 512
#define HE_ 512
#define HD_ 1024
#define T_ 128
#define LN_ (L_*N_)
#define G4E_ 2048
#define NB_ 128u

// ---------------- scratch (device globals) ----------------
__device__ __align__(16) float g_xs[LN_*E_];
__device__ __align__(16) float g_G[2][(size_t)LN_*G4E_];
__device__ __align__(16) float g_h1[(size_t)LN_*2*HE_];          // enc0 output (normal, feeds enc1 input GEMM)
__device__ __align__(16) float g_encT4[(size_t)L_*(2*HE_/4)*N_*4]; // enc1 output, k-packed transposed [t][u4][n][4]
__device__ __align__(16) float g_ehT4[2][2][(HE_/4)*N_*4];       // enc h state [phase][dir][k4][n][4]
__device__ __align__(16) float g_ec[2][N_*HE_];                  // enc cell [dir]
__device__ __align__(16) float g_dhT4[2][(HD_/4)*N_*4];          // dec h transposed (GEMM operand)
__device__ __align__(16) float g_dh[2][N_*HD_];                  // dec h normal (logits operand)
__device__ __align__(16) float g_dc[N_*HD_];
__device__ __align__(16) float g_wiT[T_][4*HD_];                 // transposed dec_wih
__device__ int   g_amax[N_];
__device__ float g_lterm[L_*N_];

__device__ unsigned g_bcnt = 0;
__device__ volatile unsigned g_bgen = 0;

__device__ __forceinline__ void fma2(ull& d, ull a, ull b){
    asm("fma.rn.f32x2 %0, %1, %2, %0;" : "+l"(d) : "l"(a), "l"(b));
}
__device__ __forceinline__ ull dup2(float x){
    ull r; asm("mov.b64 %0, {%1, %1};" : "=l"(r) : "f"(x)); return r;
}
__device__ __forceinline__ float2 unpack2(ull v){
    float2 r; asm("mov.b64 {%0, %1}, %2;" : "=f"(r.x), "=f"(r.y) : "l"(v)); return r;
}
__device__ __forceinline__ float sigf(float x){ return 1.f/(1.f+expf(-x)); }

__device__ __forceinline__ void gridbar(){
    __syncthreads();
    if (threadIdx.x == 0) {
        unsigned g = g_bgen;
        __threadfence();
        if (atomicAdd(&g_bcnt, 1u) == NB_ - 1u) {
            atomicExch(&g_bcnt, 0u);
            __threadfence();
            g_bgen = g + 1u;
        } else {
            while (g_bgen == g) { }
        }
        __threadfence();
    }
    __syncthreads();
}

// ---------------- embedding ----------------
__global__ void k_embed(const int* __restrict__ ids, const float* __restrict__ embed)
{
    int i = blockIdx.x*blockDim.x + threadIdx.x;
    const int tot = LN_*E_/4;
    if (i >= tot) return;
    int e4 = i % (E_/4);
    int ln = i / (E_/4);
    int l = ln / N_, n = ln % N_;
    int id = ids[n*L_ + l];
    reinterpret_cast<float4*>(g_xs)[i] =
        reinterpret_cast<const float4*>(embed + (size_t)id*E_)[e4];
}

// ---------------- dwih transpose ----------------
__global__ void k_wiT(const float* __restrict__ dwih)
{
    int i = blockIdx.x*blockDim.x + threadIdx.x;
    if (i < 4*HD_*T_) {
        int col = i >> 7;
        int idx = i & 127;
        g_wiT[idx][col] = dwih[i];
    }
}

// ---------------- big input GEMM (stable R9+ version, fma 66%) ----------------
__global__ __launch_bounds__(256) void k_gemm_bias(int asel, const float* __restrict__ Ball,
                                                   const float* __restrict__ biasall, int K)
{
    const float* A = asel ? g_h1 : g_xs;
    int z = blockIdx.z;
    const float* B = Ball + (size_t)z * G4E_ * K;
    const float* bias = biasall + z * G4E_;
    float* C = g_G[z];
    int m0 = blockIdx.y * 128, n0 = blockIdx.x * 128;
    __shared__ float As[8][132];
    __shared__ float Bs[8][132];
    int tid = threadIdx.x;
    int lr = tid >> 1, lk = (tid & 1) * 4;
    int ry = (tid >> 4) * 8;
    int c4 = (tid & 15) * 4;
    ull acc[4][8];
    #pragma unroll
    for (int p = 0; p < 4; p++)
        #pragma unroll
        for (int j = 0; j < 8; j++) acc[p][j] = 0ull;
    const float* Arow = A + (size_t)(m0+lr)*K + lk;
    const float* Brow = B + (size_t)(n0+lr)*K + lk;
    #pragma unroll 1
    for (int kc = 0; kc < K; kc += 8) {
        float4 av = *(const float4*)(Arow + kc);
        float4 bv = *(const float4*)(Brow + kc);
        __syncthreads();
        As[lk+0][lr]=av.x; As[lk+1][lr]=av.y; As[lk+2][lr]=av.z; As[lk+3][lr]=av.w;
        Bs[lk+0][lr]=bv.x; Bs[lk+1][lr]=bv.y; Bs[lk+2][lr]=bv.z; Bs[lk+3][lr]=bv.w;
        __syncthreads();
        #pragma unroll
        for (int kk = 0; kk < 8; kk++) {
            ulonglong2 aA = *(const ulonglong2*)&As[kk][ry];
            ulonglong2 aB = *(const ulonglong2*)&As[kk][ry+4];
            float4 b0 = *(const float4*)&Bs[kk][c4];
            float4 b1 = *(const float4*)&Bs[kk][64+c4];
            ull q[8] = {dup2(b0.x),dup2(b0.y),dup2(b0.z),dup2(b0.w),
                        dup2(b1.x),dup2(b1.y),dup2(b1.z),dup2(b1.w)};
            ull ar[4] = {aA.x, aA.y, aB.x, aB.y};
            #pragma unroll
            for (int p = 0; p < 4; p++)
                #pragma unroll
                for (int j = 0; j < 8; j++)
                    fma2(acc[p][j], ar[p], q[j]);
        }
    }
    float4 bia0 = *(const float4*)(bias + n0 + c4);
    float4 bia1 = *(const float4*)(bias + n0 + 64 + c4);
    #pragma unroll
    for (int p = 0; p < 4; p++) {
        float2 v[8];
        #pragma unroll
        for (int j = 0; j < 8; j++) v[j] = unpack2(acc[p][j]);
        float* C0 = C + (size_t)(m0+ry+2*p)*G4E_ + n0;
        float* C1 = C + (size_t)(m0+ry+2*p+1)*G4E_ + n0;
        *(float4*)(C0 + c4)    = make_float4(v[0].x+bia0.x, v[1].x+bia0.y, v[2].x+bia0.z, v[3].x+bia0.w);
        *(float4*)(C0 + 64+c4) = make_float4(v[4].x+bia1.x, v[5].x+bia1.y, v[6].x+bia1.z, v[7].x+bia1.w);
        *(float4*)(C1 + c4)    = make_float4(v[0].y+bia0.x, v[1].y+bia0.y, v[2].y+bia0.z, v[3].y+bia0.w);
        *(float4*)(C1 + 64+c4) = make_float4(v[4].y+bia1.x, v[5].y+bia1.y, v[6].y+bia1.z, v[7].y+bia1.w);
    }
}

// ================= persistent encoder: warp-autonomous GEMM on transposed h =================
// 128 blocks x 512 threads. Block b: d = b>>6, u0 = (b&63)*8 (8 units x 4 gates = 32 cols).
// Warp w: rg = w&3 (rows rg*32+lane), kg = w>>2 (K quarter). No staging, 4-sync reduction.
__global__ __launch_bounds__(512) void k_encP(int layer, const float* __restrict__ whh_all)
{
    extern __shared__ float sm[];
    float* Bs = sm;                        // [512][36]
    float* gs = sm + 512*36;               // [128][36]

    const int b  = blockIdx.x;
    const int d  = b >> 6;
    const int u0 = (b & 63) * 8;
    const int tid = threadIdx.x;
    const int w  = tid >> 5, lane = tid & 31;
    const int rg = w & 3, kg = w >> 2;
    const int nn = rg*32 + lane;           // this lane's row (sample)

    // stage resident weights: Bs[k*36 + c], c = gate*8+uu -> wr = gate*HE + u0 + uu
    {
        const float* wb = whh_all + (size_t)d * (4*HE_) * HE_;
        for (int s = tid; s < 32*(HE_/4); s += 512) {
            int c = s / (HE_/4), k4 = s % (HE_/4);
            int wr = (c >> 3) * HE_ + u0 + (c & 7);
            float4 v = *(const float4*)(wb + (size_t)wr*HE_ + k4*4);
            Bs[(k4*4+0)*36 + c] = v.x;
            Bs[(k4*4+1)*36 + c] = v.y;
            Bs[(k4*4+2)*36 + c] = v.z;
            Bs[(k4*4+3)*36 + c] = v.w;
        }
    }
    __syncthreads();

    for (int t = 0; t < L_; t++) {
        const int t_eff = d ? (L_-1-t) : t;
        ull acc[16];
        #pragma unroll
        for (int i = 0; i < 16; i++) acc[i] = 0ull;

        if (t > 0) {
            const float* AT = &g_ehT4[t & 1][d][0];
            const float* ap = AT + (size_t)(kg*32)*(N_*4) + nn*4;
            float4 avn = __ldcg((const float4*)ap);
            #pragma unroll 1
            for (int it = 0; it < 32; it++) {
                float4 av = avn;
                if (it + 1 < 32) avn = __ldcg((const float4*)(ap + (it+1)*(N_*4)));
                const float* brow = Bs + (kg*32 + it)*4*36;
                float a_[4] = {av.x, av.y, av.z, av.w};
                #pragma unroll
                for (int e = 0; e < 4; e++) {
                    ull ad = dup2(a_[e]);
                    const ulonglong2* bq = (const ulonglong2*)(brow + e*36);
                    #pragma unroll
                    for (int i = 0; i < 8; i++) {
                        ulonglong2 u = bq[i];
                        fma2(acc[2*i],   ad, u.x);
                        fma2(acc[2*i+1], ad, u.y);
                    }
                }
            }
        }
        // 4-phase K-group reduction into gs
        #pragma unroll 1
        for (int p = 0; p < 4; p++) {
            if (kg == p) {
                #pragma unroll
                for (int i = 0; i < 8; i++) {
                    float2 v0 = unpack2(acc[2*i]);
                    float2 v1 = unpack2(acc[2*i+1]);
                    float4 val = make_float4(v0.x, v0.y, v1.x, v1.y);
                    float* wp = gs + nn*36 + 4*i;
                    if (p == 0) *(float4*)wp = val;
                    else {
                        float4 o = *(const float4*)wp;
                        *(float4*)wp = make_float4(o.x+val.x, o.y+val.y, o.z+val.z, o.w+val.w);
                    }
                }
            }
            __syncthreads();
        }
        // epilogue (first 256 threads)
        if (tid < 256) {
            int row = tid >> 1;
            int uu0 = (tid & 1) * 4;
            int n2 = row;
            const float* Gp = g_G[d] + ((size_t)t_eff*N_ + n2)*G4E_ + u0 + uu0;
            float4 Gi = *(const float4*)(Gp);
            float4 Gf = *(const float4*)(Gp + HE_);
            float4 Gc = *(const float4*)(Gp + 2*HE_);
            float4 Go = *(const float4*)(Gp + 3*HE_);
            float4 si = *(const float4*)&gs[row*36 + uu0];
            float4 sf = *(const float4*)&gs[row*36 + 8 + uu0];
            float4 sc = *(const float4*)&gs[row*36 + 16 + uu0];
            float4 so = *(const float4*)&gs[row*36 + 24 + uu0];
            float* cp = &g_ec[d][n2*HE_ + u0 + uu0];
            float4 cv = (t > 0) ? *(const float4*)cp : make_float4(0.f,0.f,0.f,0.f);
            float4 cn, hn;
            cn.x = sigf(Gf.x+sf.x)*cv.x + sigf(Gi.x+si.x)*tanhf(Gc.x+sc.x);
            cn.y = sigf(Gf.y+sf.y)*cv.y + sigf(Gi.y+si.y)*tanhf(Gc.y+sc.y);
            cn.z = sigf(Gf.z+sf.z)*cv.z + sigf(Gi.z+si.z)*tanhf(Gc.z+sc.z);
            cn.w = sigf(Gf.w+sf.w)*cv.w + sigf(Gi.w+si.w)*tanhf(Gc.w+sc.w);
            hn.x = sigf(Go.x+so.x)*tanhf(cn.x);
            hn.y = sigf(Go.y+so.y)*tanhf(cn.y);
            hn.z = sigf(Go.z+so.z)*tanhf(cn.z);
            hn.w = sigf(Go.w+so.w)*tanhf(cn.w);
            *(float4*)cp = cn;
            // transposed h for next step's GEMM
            *(float4*)(&g_ehT4[1-(t&1)][d][0] + (size_t)((u0+uu0)>>2)*(N_*4) + n2*4) = hn;
            // layer output
            if (layer == 0) {
                *(float4*)&g_h1[(size_t)t_eff*(N_*2*HE_) + (size_t)n2*(2*HE_) + d*HE_ + u0 + uu0] = hn;
            } else {
                *(float4*)(g_encT4 + (size_t)t_eff*((2*HE_/4)*N_*4)
                           + (size_t)((d*HE_ + u0 + uu0)>>2)*(N_*4) + n2*4) = hn;
            }
        }
        gridbar();
    }
}

// ---------------- decoder init ----------------
__global__ void k_dec_init()
{
    int i = blockIdx.x*blockDim.x + threadIdx.x;
    if (i < N_*HD_) {
        int n = i / HD_, k = i % HD_;
        int uu = HE_ + (k & (HE_-1));
        g_dc[i] = g_encT4[(size_t)(uu>>2)*(N_*4) + n*4 + (uu & 3)];
        g_dh[0][i] = 0.f;
        ((float*)g_dhT4)[i] = 0.f;   // g_dhT4[0] has exactly N_*HD_ floats
    }
}

// ================= persistent decoder: warp-autonomous GEMM on transposed h =================
__global__ __launch_bounds__(512) void k_decP(const float* __restrict__ dwhh,
        const float* __restrict__ db,
        const float* __restrict__ ow, const float* __restrict__ obv,
        const int* __restrict__ tags, float* __restrict__ out)
{
    extern __shared__ float sm[];
    float* Bs = sm;                        // [1024][36]
    float* gs = sm + 1024*36;              // [128][36]  (logits overlay lives here too)
    float* hsv = gs;                       // [1024]
    float* lg  = gs + 1024;                // [128]
    float* red = lg + 128;                 // [128]
    int*  redi = (int*)(red + 128);        // [128]

    const int b  = blockIdx.x;
    const int u0 = b * 8;
    const int tid = threadIdx.x;
    const int w  = tid >> 5, lane = tid & 31;
    const int rg = w & 3, kg = w >> 2;
    const int nn = rg*32 + lane;

    for (int s = tid; s < 32*(HD_/4); s += 512) {
        int c = s / (HD_/4), k4 = s % (HD_/4);
        int wr = (c >> 3) * HD_ + u0 + (c & 7);
        float4 v = *(const float4*)(dwhh + (size_t)wr*HD_ + k4*4);
        Bs[(k4*4+0)*36 + c] = v.x;
        Bs[(k4*4+1)*36 + c] = v.y;
        Bs[(k4*4+2)*36 + c] = v.z;
        Bs[(k4*4+3)*36 + c] = v.w;
    }
    __syncthreads();

    for (int t = 0; t < L_; t++) {
        const int ph = t & 1;
        ull acc[16];
        #pragma unroll
        for (int i = 0; i < 16; i++) acc[i] = 0ull;
        // ---- warp-autonomous GEMM: A = (h_prev + enc[t]) in T4 layout ----
        {
            const float* hT = &g_dhT4[ph][0] + (size_t)(kg*64)*(N_*4) + nn*4;
            const float* eT = g_encT4 + (size_t)t*((2*HE_/4)*N_*4) + (size_t)(kg*64)*(N_*4) + nn*4;
            float4 hn_ = __ldcg((const float4*)hT);
            float4 en_ = __ldcg((const float4*)eT);
            #pragma unroll 1
            for (int it = 0; it < 64; it++) {
                float4 hv = hn_, ev = en_;
                if (it + 1 < 64) {
                    hn_ = __ldcg((const float4*)(hT + (it+1)*(N_*4)));
                    en_ = __ldcg((const float4*)(eT + (it+1)*(N_*4)));
                }
                float a_[4] = {hv.x+ev.x, hv.y+ev.y, hv.z+ev.z, hv.w+ev.w};
                const float* brow = Bs + (kg*64 + it)*4*36;
                #pragma unroll
                for (int e = 0; e < 4; e++) {
                    ull ad = dup2(a_[e]);
                    const ulonglong2* bq = (const ulonglong2*)(brow + e*36);
                    #pragma unroll
                    for (int i = 0; i < 8; i++) {
                        ulonglong2 u = bq[i];
                        fma2(acc[2*i],   ad, u.x);
                        fma2(acc[2*i+1], ad, u.y);
                    }
                }
            }
        }
        // 4-phase reduction
        #pragma unroll 1
        for (int p = 0; p < 4; p++) {
            if (kg == p) {
                #pragma unroll
                for (int i = 0; i < 8; i++) {
                    float2 v0 = unpack2(acc[2*i]);
                    float2 v1 = unpack2(acc[2*i+1]);
                    float4 val = make_float4(v0.x, v0.y, v1.x, v1.y);
                    float* wp = gs + nn*36 + 4*i;
                    if (p == 0) *(float4*)wp = val;
                    else {
                        float4 o = *(const float4*)wp;
                        *(float4*)wp = make_float4(o.x+val.x, o.y+val.y, o.z+val.z, o.w+val.w);
                    }
                }
            }
            __syncthreads();
        }
        // ---- epilogue (first 256 threads) ----
        if (tid < 256) {
            int row = tid >> 1;
            int uu0 = (tid & 1) * 4;
            int n2 = row;
            float4 si = *(const float4*)&gs[row*36 + uu0];
            float4 sf = *(const float4*)&gs[row*36 + 8 + uu0];
            float4 sc = *(const float4*)&gs[row*36 + 16 + uu0];
            float4 so = *(const float4*)&gs[row*36 + 24 + uu0];
            float4 bi = *(const float4*)(db + u0 + uu0);
            float4 bf = *(const float4*)(db + HD_ + u0 + uu0);
            float4 bc = *(const float4*)(db + 2*HD_ + u0 + uu0);
            float4 bo = *(const float4*)(db + 3*HD_ + u0 + uu0);
            float4 wi0 = make_float4(0.f,0.f,0.f,0.f), wi1 = wi0, wi2 = wi0, wi3 = wi0;
            if (t > 0) {
                int am = __ldcg(&g_amax[n2]);
                const float* wr_ = g_wiT[am] + u0 + uu0;
                wi0 = *(const float4*)(wr_);
                wi1 = *(const float4*)(wr_ + HD_);
                wi2 = *(const float4*)(wr_ + 2*HD_);
                wi3 = *(const float4*)(wr_ + 3*HD_);
            }
            float gi[4] = {si.x+bi.x+wi0.x, si.y+bi.y+wi0.y, si.z+bi.z+wi0.z, si.w+bi.w+wi0.w};
            float gf[4] = {sf.x+bf.x+wi1.x, sf.y+bf.y+wi1.y, sf.z+bf.z+wi1.z, sf.w+bf.w+wi1.w};
            float gc[4] = {sc.x+bc.x+wi2.x, sc.y+bc.y+wi2.y, sc.z+bc.z+wi2.z, sc.w+bc.w+wi2.w};
            float go[4] = {so.x+bo.x+wi3.x, so.y+bo.y+wi3.y, so.z+bo.z+wi3.z, so.w+bo.w+wi3.w};
            float* cp = &g_dc[n2*HD_ + u0 + uu0];
            float4 cv = *(const float4*)cp;
            float4 cn, hn;
            cn.x = sigf(gf[0])*cv.x + sigf(gi[0])*tanhf(gc[0]);
            cn.y = sigf(gf[1])*cv.y + sigf(gi[1])*tanhf(gc[1]);
            cn.z = sigf(gf[2])*cv.z + sigf(gi[2])*tanhf(gc[2]);
            cn.w = sigf(gf[3])*cv.w + sigf(gi[3])*tanhf(gc[3]);
            hn.x = sigf(go[0])*tanhf(cn.x);
            hn.y = sigf(go[1])*tanhf(cn.y);
            hn.z = sigf(go[2])*tanhf(cn.z);
            hn.w = sigf(go[3])*tanhf(cn.w);
            *(float4*)cp = cn;
            *(float4*)&g_dh[1-ph][n2*HD_ + u0 + uu0] = hn;
            *(float4*)(&g_dhT4[1-ph][0] + (size_t)((u0+uu0)>>2)*(N_*4) + n2*4) = hn;
        }
        gridbar();
        // ---- logits / softmax / argmax: block b = sample n ----
        {
            const int n = b;
            const float* hsrc = g_dh[1-ph] + (size_t)n*HD_;
            for (int k = tid; k < HD_; k += 512) hsv[k] = __ldcg(hsrc + k);
            __syncthreads();
            {
                int ww = tid >> 5, lane2 = tid & 31;
                #pragma unroll 1
                for (int rr = 0; rr < 8; rr++) {
                    int j = ww*8 + rr;
                    const float* wrow = ow + (size_t)j*HD_ + lane2*4;
                    const float* hh = hsv + lane2*4;
                    ull s0 = 0ull, s1 = 0ull;
                    #pragma unroll
                    for (int i = 0; i < 8; i++) {
                        ulonglong2 wp = *(const ulonglong2*)(wrow + i*128);
                        ulonglong2 hp = *(const ulonglong2*)(hh + i*128);
                        fma2(s0, wp.x, hp.x);
                        fma2(s1, wp.y, hp.y);
                    }
                    float2 q0 = unpack2(s0), q1 = unpack2(s1);
                    float p = (q0.x + q0.y) + (q1.x + q1.y);
                    #pragma unroll
                    for (int off = 16; off > 0; off >>= 1)
                        p += __shfl_down_sync(0xffffffffu, p, off);
                    if (lane2 == 0) lg[j] = p + obv[j];
                }
            }
            __syncthreads();
            if (tid < 128) red[tid] = lg[tid];
            __syncthreads();
            for (int s = 64; s > 0; s >>= 1) { if (tid < s) red[tid] = fmaxf(red[tid], red[tid+s]); __syncthreads(); }
            float mx = red[0]; __syncthreads();
            float accv = 0.f, ev = 0.f;
            if (tid < 128) { accv = lg[tid]; ev = expf(accv - mx); red[tid] = ev; }
            __syncthreads();
            for (int s = 64; s > 0; s >>= 1) { if (tid < s) red[tid] += red[tid+s]; __syncthreads(); }
            float sum = red[0];
            if (tid < 128) out[((size_t)n*L_ + t)*T_ + tid] = ev / sum;
            int tag = tags[n*L_ + t];
            if (tid == tag) g_lterm[t*N_ + n] = -(accv - mx - logf(sum)) / (float)N_;
            __syncthreads();
            if (tid < 128) { red[tid] = lg[tid]; redi[tid] = tid; }
            __syncthreads();
            for (int s = 64; s > 0; s >>= 1) {
                if (tid < s) {
                    float o = red[tid+s]; int oi = redi[tid+s];
                    if (o > red[tid] || (o == red[tid] && oi < redi[tid])) { red[tid] = o; redi[tid] = oi; }
                }
                __syncthreads();
            }
            if (tid == 0) g_amax[n] = redi[0];
        }
        gridbar();
    }
}

// ---------------- deterministic loss reduction ----------------
__global__ void k_loss(float* __restrict__ out)
{
    __shared__ float red[256];
    float s = 0.f;
    for (int i = threadIdx.x; i < L_*N_; i += 256) s += g_lterm[i];
    red[threadIdx.x] = s; __syncthreads();
    for (int st = 128; st > 0; st >>= 1) {
        if (threadIdx.x < st) red[threadIdx.x] += red[threadIdx.x + st];
        __syncthreads();
    }
    if (threadIdx.x == 0) out[(size_t)N_*L_*T_] = red[0];
}

// ---------------- launcher ----------------
#define ENC_SMEM ((512*36 + 128*36)*4)
#define DEC_SMEM ((1024*36 + 128*36)*4)

extern "C" void kernel_launch(void* const* d_in, const int* in_sizes, int n_in,
                              void* d_out, int out_size)
{
    const int*   ids    = (const int*)  d_in[0];
    const int*   tags   = (const int*)  d_in[1];
    const float* embed  = (const float*)d_in[2];
    const float* e0_wih = (const float*)d_in[3];
    const float* e0_whh = (const float*)d_in[4];
    const float* e0_b   = (const float*)d_in[5];
    const float* e1_wih = (const float*)d_in[6];
    const float* e1_whh = (const float*)d_in[7];
    const float* e1_b   = (const float*)d_in[8];
    const float* dwih   = (const float*)d_in[9];
    const float* dwhh   = (const float*)d_in[10];
    const float* db     = (const float*)d_in[11];
    const float* ow     = (const float*)d_in[12];
    const float* obv    = (const float*)d_in[13];
    float* out = (float*)d_out;

    cudaFuncSetAttribute(k_encP, cudaFuncAttributeMaxDynamicSharedMemorySize, ENC_SMEM);
    cudaFuncSetAttribute(k_decP, cudaFuncAttributeMaxDynamicSharedMemorySize, DEC_SMEM);

    // 1. embedding + dwih transpose
    k_embed<<<(LN_*E_/4 + 255)/256, 256>>>(ids, embed);
    k_wiT<<<(4*HD_*T_ + 255)/256, 256>>>(dwih);

    // 2. enc0
    {
        dim3 gg(G4E_/128, LN_/128, 2);
        k_gemm_bias<<<gg, 256>>>(0, e0_wih, e0_b, E_);
    }
    k_encP<<<NB_, 512, ENC_SMEM>>>(0, e0_whh);

    // 3. enc1
    {
        dim3 gg(G4E_/128, LN_/128, 2);
        k_gemm_bias<<<gg, 256>>>(1, e1_wih, e1_b, 2*HE_);
    }
    k_encP<<<NB_, 512, ENC_SMEM>>>(1, e1_whh);

    // 4. decoder
    k_dec_init<<<(N_*HD_ + 255)/256, 256>>>();
    k_decP<<<NB_, 512, DEC_SMEM>>>(dwhh, db, ow, obv, tags, out);

    // 5. loss
    k_loss<<<1, 256>>>(out);
}